// round 7
// baseline (speedup 1.0000x reference)
#include <cuda_runtime.h>

typedef unsigned long long ull;

// ---------------- scratch (static device globals; no allocations) ----------------
__device__ float g_act1[800ull * 64 * 42 * 42];   // 361 MB
__device__ float g_act2[800ull * 64 * 21 * 21];   // 90 MB
__device__ float g_act3[800ull * 64 * 11 * 11];   // 25 MB
__device__ float g_emb [800ull * 2304];           // 7.4 MB
__device__ float g_w1t [3  * 9 * 64];
__device__ float g_w2t [64 * 9 * 64];
__device__ float g_w3t [64 * 9 * 64];
__device__ float g_w4t [64 * 9 * 64];
__device__ float g_protos[8 * 5 * 2304];
__device__ float g_pnorm[40];

// ---------------- packed f32x2 helpers (FFMA2: 2x fp32 FMA rate) ----------------
__device__ __forceinline__ void ffma2(ull &d, ull a, ull b) {
    asm("fma.rn.f32x2 %0, %1, %2, %0;" : "+l"(d) : "l"(a), "l"(b));
}
__device__ __forceinline__ ull pack2(float v) {
    ull r; asm("mov.b64 %0, {%1, %1};" : "=l"(r) : "f"(v)); return r;
}
__device__ __forceinline__ float2 unpack2(ull a) {
    float2 f; asm("mov.b64 {%0, %1}, %2;" : "=f"(f.x), "=f"(f.y) : "l"(a)); return f;
}

// ---------------- weight transposes (all 4 layers in one launch) ----------------
// OIHW [oc][ic][kh][kw] -> [ic][k][oc]
__global__ void transpose_all(const float* __restrict__ W1, float* __restrict__ o1,
                              const float* __restrict__ W2, float* __restrict__ o2,
                              const float* __restrict__ W3, float* __restrict__ o3,
                              const float* __restrict__ W4, float* __restrict__ o4)
{
    int i = blockIdx.x * blockDim.x + threadIdx.x;
    if (i < 1728) {
        int oc = i / 27, rem = i % 27, ic = rem / 9, k = rem % 9;
        o1[(ic * 9 + k) * 64 + oc] = W1[i];
    }
    if (i < 36864) {
        int oc = i / 576, rem = i % 576, ic = rem / 9, k = rem % 9;
        o2[(ic * 9 + k) * 64 + oc] = W2[i];
        o3[(ic * 9 + k) * 64 + oc] = W3[i];
        o4[(ic * 9 + k) * 64 + oc] = W4[i];
    }
}

// ---------------- register-tiled direct conv (3x3, stride 2, relu) ----------------
// in : [nimg][CIN][IN_HW][IN_HW]  (layer 1 reads two tensors via SPLIT)
// wt : transposed weights [CIN][9][64]
// out: [nimg][64][OUT_HW][OUT_HW]
// Row register-caching: per (icc,kh) the contiguous input segment covering all
// three kw taps is loaded once (float2 LDS.64), then replayed from registers.
template<int CIN, int ICC, int IN_HW, int OUT_HW, int PAD, int RB, int TN, int CT, int SPLIT>
__global__ void conv_k(const float* __restrict__ inA, const float* __restrict__ inB,
                       const float* __restrict__ wt,
                       const float* __restrict__ bias, float* __restrict__ out)
{
    constexpr int IN_ROWS = 2 * RB + 1;
    constexpr int W2E = (IN_HW + 4 + 3) & ~3;   // padded row stride (float2/float4 aligned)
    constexpr int SPT = RB * CT;

    __shared__ __align__(16) float s_in[ICC * IN_ROWS * W2E];
    __shared__ __align__(16) float s_w[ICC * 9 * 64];

    const int img   = blockIdx.x;
    const int r0    = blockIdx.y * RB;
    const int tid   = threadIdx.x;
    const int ocg   = tid / SPT;           // 0..7
    const int spt   = tid % SPT;
    const int orow  = spt / CT;            // 0..RB-1
    const int ocol0 = (spt % CT) * TN;
    const int oc0   = ocg * 8;

    ull acc[4][TN];
#pragma unroll
    for (int p = 0; p < 4; p++)
#pragma unroll
        for (int t = 0; t < TN; t++) acc[p][t] = 0ull;

    const float* inb;
    if (SPLIT && img >= SPLIT)
        inb = inB + (size_t)(img - SPLIT) * CIN * IN_HW * IN_HW;
    else
        inb = inA + (size_t)img * CIN * IN_HW * IN_HW;

    for (int ic0 = 0; ic0 < CIN; ic0 += ICC) {
        // stage input tile (zero-padded borders + zero pad columns)
        for (int i = tid; i < ICC * IN_ROWS * W2E; i += blockDim.x) {
            int c   = i % W2E;
            int r   = (i / W2E) % IN_ROWS;
            int icc = i / (W2E * IN_ROWS);
            int gr  = 2 * r0 - PAD + r;
            int gc  = c - PAD;
            float v = 0.f;
            if ((unsigned)gr < (unsigned)IN_HW && (unsigned)gc < (unsigned)IN_HW)
                v = inb[((size_t)(ic0 + icc) * IN_HW + gr) * IN_HW + gc];
            s_in[i] = v;
        }
        // stage weights chunk
        for (int i = tid; i < ICC * 9 * 64; i += blockDim.x)
            s_w[i] = wt[ic0 * 9 * 64 + i];
        __syncthreads();

#pragma unroll
        for (int icc = 0; icc < ICC; icc++) {
            const float* rowbase = s_in + (icc * IN_ROWS + 2 * orow) * W2E + 2 * ocol0;
            const float* swc     = s_w + icc * 576 + oc0;
#pragma unroll
            for (int kh = 0; kh < 3; kh++) {
                // cache full needed row segment: columns [0 .. 2*TN] (+1 spare)
                float rows[2 * TN + 2];
                const float* rp = rowbase + kh * W2E;   // 8B-aligned (all terms even)
#pragma unroll
                for (int j = 0; j <= TN; j++) {
                    float2 rr = *(const float2*)(rp + 2 * j);
                    rows[2 * j]     = rr.x;
                    rows[2 * j + 1] = rr.y;
                }
#pragma unroll
                for (int kw = 0; kw < 3; kw++) {
                    const ulonglong2* wv = (const ulonglong2*)(swc + (kh * 3 + kw) * 64);
                    ulonglong2 wa = wv[0];     // LDS.128: oc pairs 0-3
                    ulonglong2 wb = wv[1];     // LDS.128: oc pairs 4-7
#pragma unroll
                    for (int t = 0; t < TN; t++) {
                        ull vv = pack2(rows[2 * t + kw]);
                        ffma2(acc[0][t], vv, wa.x);
                        ffma2(acc[1][t], vv, wa.y);
                        ffma2(acc[2][t], vv, wb.x);
                        ffma2(acc[3][t], vv, wb.y);
                    }
                }
            }
        }
        __syncthreads();
    }

    // epilogue: bias + relu, write NCHW
    const int oh = r0 + orow;
    float* ob = out + (size_t)img * 64 * OUT_HW * OUT_HW;
#pragma unroll
    for (int p = 0; p < 4; p++) {
        float blo = bias[oc0 + 2 * p];
        float bhi = bias[oc0 + 2 * p + 1];
#pragma unroll
        for (int t = 0; t < TN; t++) {
            int ow = ocol0 + t;
            if ((OUT_HW % TN) != 0 && ow >= OUT_HW) continue;
            float2 v = unpack2(acc[p][t]);
            ob[((size_t)(oc0 + 2 * p)     * OUT_HW + oh) * OUT_HW + ow] = fmaxf(v.x + blo, 0.f);
            ob[((size_t)(oc0 + 2 * p + 1) * OUT_HW + oh) * OUT_HW + ow] = fmaxf(v.y + bhi, 0.f);
        }
    }
}

// ---------------- prototypes: segment-sum over classes / CAP(=5) ----------------
__global__ void proto_kernel(const float* __restrict__ emb_s, const int* __restrict__ y,
                             float* __restrict__ protos)
{
    int b = blockIdx.x, c = blockIdx.y;
    for (int d = threadIdx.x; d < 2304; d += blockDim.x) {
        float acc = 0.f;
#pragma unroll
        for (int s = 0; s < 25; s++) {
            if ((y[b * 25 + s] % 5) == c)
                acc += emb_s[(size_t)(b * 25 + s) * 2304 + d];
        }
        protos[(size_t)(b * 5 + c) * 2304 + d] = acc * 0.2f;
    }
}

__device__ __forceinline__ float block_reduce(float v, float* red) {
    red[threadIdx.x] = v;
    __syncthreads();
    for (int s = 128; s > 0; s >>= 1) {
        if (threadIdx.x < s) red[threadIdx.x] += red[threadIdx.x + s];
        __syncthreads();
    }
    float r = red[0];
    __syncthreads();
    return r;
}

__global__ void pnorm_kernel(const float* __restrict__ protos, float* __restrict__ pnorm) {
    __shared__ float red[256];
    const float* p = protos + (size_t)blockIdx.x * 2304;
    float s = 0.f;
    for (int d = threadIdx.x; d < 2304; d += 256) { float v = p[d]; s += v * v; }
    float tot = block_reduce(s, red);
    if (threadIdx.x == 0) pnorm[blockIdx.x] = fmaxf(sqrtf(tot), 1e-8f);
}

// ---------------- cosine-similarity logits ----------------
__global__ void logits_kernel(const float* __restrict__ emb, const float* __restrict__ protos,
                              const float* __restrict__ pnorm, float* __restrict__ out)
{
    __shared__ float red[256];
    int b = blockIdx.x / 75, t = blockIdx.x % 75;
    const float* q = emb + (size_t)(200 + b * 75 + t) * 2304;
    const float* P = protos + (size_t)b * 5 * 2304;

    float q2 = 0.f, dot[5] = {0.f, 0.f, 0.f, 0.f, 0.f};
    for (int d = threadIdx.x; d < 2304; d += 256) {
        float v = q[d];
        q2 += v * v;
#pragma unroll
        for (int c = 0; c < 5; c++) dot[c] += v * P[(size_t)c * 2304 + d];
    }
    float q2t = block_reduce(q2, red);
    float qn  = fmaxf(sqrtf(q2t), 1e-8f);
#pragma unroll
    for (int c = 0; c < 5; c++) {
        float dt = block_reduce(dot[c], red);
        if (threadIdx.x == 0)
            out[(size_t)(b * 75 + t) * 5 + c] = dt / (qn * pnorm[b * 5 + c]);
    }
}

// ---------------- launch ----------------
extern "C" void kernel_launch(void* const* d_in, const int* in_sizes, int n_in,
                              void* d_out, int out_size)
{
    const float* xs = (const float*)d_in[0];   // [8,25,3,84,84]
    const float* xt = (const float*)d_in[1];   // [8,75,3,84,84]
    const int*   y  = (const int*)  d_in[2];   // [8,25]
    const float* W1 = (const float*)d_in[3];
    const float* b1 = (const float*)d_in[4];
    const float* W2 = (const float*)d_in[5];
    const float* b2 = (const float*)d_in[6];
    const float* W3 = (const float*)d_in[7];
    const float* b3 = (const float*)d_in[8];
    const float* W4 = (const float*)d_in[9];
    const float* b4 = (const float*)d_in[10];
    float* out = (float*)d_out;

    float *act1, *act2, *act3, *emb, *w1t, *w2t, *w3t, *w4t, *protos, *pnorm;
    cudaGetSymbolAddress((void**)&act1,   g_act1);
    cudaGetSymbolAddress((void**)&act2,   g_act2);
    cudaGetSymbolAddress((void**)&act3,   g_act3);
    cudaGetSymbolAddress((void**)&emb,    g_emb);
    cudaGetSymbolAddress((void**)&w1t,    g_w1t);
    cudaGetSymbolAddress((void**)&w2t,    g_w2t);
    cudaGetSymbolAddress((void**)&w3t,    g_w3t);
    cudaGetSymbolAddress((void**)&w4t,    g_w4t);
    cudaGetSymbolAddress((void**)&protos, g_protos);
    cudaGetSymbolAddress((void**)&pnorm,  g_pnorm);

    transpose_all<<<(36864 + 255) / 256, 256>>>(W1, w1t, W2, w2t, W3, w3t, W4, w4t);

    // L1: 3->64, 84->42, pad_lo=0. ICC=3, RB=6, TN=7, CT=6 -> 288 thr, grid (800,7)
    conv_k<3, 3, 84, 42, 0, 6, 7, 6, 200><<<dim3(800, 7), 288>>>(xs, xt, w1t, b1, act1);
    // L2: 64->64, 42->21, pad_lo=0. ICC=8, RB=7, TN=7, CT=3 -> 168 thr, grid (800,3)
    conv_k<64, 8, 42, 21, 0, 7, 7, 3, 0><<<dim3(800, 3), 168>>>(act1, act1, w2t, b2, act2);
    // L3: 64->64, 21->11, pad_lo=1. ICC=8, RB=11, TN=6, CT=2 -> 176 thr, grid (800,1)
    conv_k<64, 8, 21, 11, 1, 11, 6, 2, 0><<<dim3(800, 1), 176>>>(act2, act2, w3t, b3, act3);
    // L4: 64->64, 11->6, pad_lo=1. ICC=8, RB=6, TN=3, CT=2 -> 96 thr, grid (800,1)
    conv_k<64, 8, 11, 6, 1, 6, 3, 2, 0><<<dim3(800, 1), 96>>>(act3, act3, w4t, b4, emb);

    proto_kernel<<<dim3(8, 5), 256>>>(emb, y, protos);
    pnorm_kernel<<<40, 256>>>(protos, pnorm);
    logits_kernel<<<600, 256>>>(emb, protos, pnorm, out);
}

// round 8
// speedup vs baseline: 1.1342x; 1.1342x over previous
#include <cuda_runtime.h>

typedef unsigned long long ull;

// ---------------- scratch (static device globals; no allocations) ----------------
__device__ float g_act1[800ull * 64 * 42 * 42];   // 361 MB
__device__ float g_act2[800ull * 64 * 21 * 21];   // 90 MB
__device__ float g_act3[800ull * 64 * 11 * 11];   // 25 MB
__device__ float g_emb [800ull * 2304];           // 7.4 MB
__device__ float g_w1t [3  * 9 * 64];
__device__ float g_w2t [64 * 9 * 64];
__device__ float g_w3t [64 * 9 * 64];
__device__ float g_w4t [64 * 9 * 64];
__device__ float g_protos[8 * 5 * 2304];
__device__ float g_pnorm[40];

// ---------------- packed f32x2 helpers (FFMA2: 2x fp32 FMA rate) ----------------
__device__ __forceinline__ void ffma2(ull &d, ull a, ull b) {
    asm("fma.rn.f32x2 %0, %1, %2, %0;" : "+l"(d) : "l"(a), "l"(b));
}
__device__ __forceinline__ ull pack2(float v) {
    ull r; asm("mov.b64 %0, {%1, %1};" : "=l"(r) : "f"(v)); return r;
}
__device__ __forceinline__ float2 unpack2(ull a) {
    float2 f; asm("mov.b64 {%0, %1}, %2;" : "=f"(f.x), "=f"(f.y) : "l"(a)); return f;
}

// ---------------- weight transposes (all 4 layers in one launch) ----------------
// OIHW [oc][ic][kh][kw] -> [ic][k][oc]
__global__ void transpose_all(const float* __restrict__ W1, float* __restrict__ o1,
                              const float* __restrict__ W2, float* __restrict__ o2,
                              const float* __restrict__ W3, float* __restrict__ o3,
                              const float* __restrict__ W4, float* __restrict__ o4)
{
    int i = blockIdx.x * blockDim.x + threadIdx.x;
    if (i < 1728) {
        int oc = i / 27, rem = i % 27, ic = rem / 9, k = rem % 9;
        o1[(ic * 9 + k) * 64 + oc] = W1[i];
    }
    if (i < 36864) {
        int oc = i / 576, rem = i % 576, ic = rem / 9, k = rem % 9;
        o2[(ic * 9 + k) * 64 + oc] = W2[i];
        o3[(ic * 9 + k) * 64 + oc] = W3[i];
        o4[(ic * 9 + k) * 64 + oc] = W4[i];
    }
}

// ---------------- register-tiled direct conv (3x3, stride 2, relu) ----------------
// in : [nimg][CIN][IN_HW][IN_HW]  (layer 1 reads two tensors via SPLIT)
// wt : transposed weights [CIN][9][64]
// out: [nimg][64][OUT_HW][OUT_HW]
// Round-2 inner loop (scalar input LDS + pack MOV), weights via LDS.128.
// TPB is warp-aligned; threads beyond 8*SPT clamp to the last oc-group
// (redundant compute) and skip the store.
template<int CIN, int ICC, int IN_HW, int OUT_HW, int PAD, int RB, int TN, int CT,
         int SPLIT, int TPB, int MINB>
__global__ void __launch_bounds__(TPB, MINB)
conv_k(const float* __restrict__ inA, const float* __restrict__ inB,
       const float* __restrict__ wt,
       const float* __restrict__ bias, float* __restrict__ out)
{
    constexpr int IN_ROWS = 2 * RB + 1;
    constexpr int W2E = (IN_HW + 4 + 3) & ~3;   // padded row stride
    constexpr int SPT = RB * CT;

    __shared__ __align__(16) float s_in[ICC * IN_ROWS * W2E];
    __shared__ __align__(16) float s_w[ICC * 9 * 64];

    const int img   = blockIdx.x;
    const int r0    = blockIdx.y * RB;
    const int tid   = threadIdx.x;
    int ocg         = tid / SPT;
    if (ocg > 7) ocg = 7;                  // clamp pad threads (redundant work)
    const int spt   = tid % SPT;
    const int orow  = spt / CT;            // 0..RB-1
    const int ocol0 = (spt % CT) * TN;
    const int oc0   = ocg * 8;

    ull acc[4][TN];
#pragma unroll
    for (int p = 0; p < 4; p++)
#pragma unroll
        for (int t = 0; t < TN; t++) acc[p][t] = 0ull;

    const float* inb;
    if (SPLIT && img >= SPLIT)
        inb = inB + (size_t)(img - SPLIT) * CIN * IN_HW * IN_HW;
    else
        inb = inA + (size_t)img * CIN * IN_HW * IN_HW;

    for (int ic0 = 0; ic0 < CIN; ic0 += ICC) {
        // stage input tile (zero-padded borders + zero pad columns)
        for (int i = tid; i < ICC * IN_ROWS * W2E; i += TPB) {
            int c   = i % W2E;
            int r   = (i / W2E) % IN_ROWS;
            int icc = i / (W2E * IN_ROWS);
            int gr  = 2 * r0 - PAD + r;
            int gc  = c - PAD;
            float v = 0.f;
            if ((unsigned)gr < (unsigned)IN_HW && (unsigned)gc < (unsigned)IN_HW)
                v = inb[((size_t)(ic0 + icc) * IN_HW + gr) * IN_HW + gc];
            s_in[i] = v;
        }
        // stage weights chunk
        for (int i = tid; i < ICC * 9 * 64; i += TPB)
            s_w[i] = wt[ic0 * 9 * 64 + i];
        __syncthreads();

#pragma unroll
        for (int icc = 0; icc < ICC; icc++) {
            const float* sin = s_in + (icc * IN_ROWS + 2 * orow) * W2E + 2 * ocol0;
            const float* swc = s_w + icc * 576 + oc0;
#pragma unroll
            for (int kh = 0; kh < 3; kh++) {
#pragma unroll
                for (int kw = 0; kw < 3; kw++) {
                    const float* srow = sin + kh * W2E + kw;
                    const ulonglong2* wv = (const ulonglong2*)(swc + (kh * 3 + kw) * 64);
                    ulonglong2 wa = wv[0];   // LDS.128: oc pairs 0-3
                    ulonglong2 wb = wv[1];   // LDS.128: oc pairs 4-7
#pragma unroll
                    for (int t = 0; t < TN; t++) {
                        ull vv = pack2(srow[2 * t]);
                        ffma2(acc[0][t], vv, wa.x);
                        ffma2(acc[1][t], vv, wa.y);
                        ffma2(acc[2][t], vv, wb.x);
                        ffma2(acc[3][t], vv, wb.y);
                    }
                }
            }
        }
        __syncthreads();
    }

    // epilogue: bias + relu, write NCHW (pad threads skip)
    if (tid < 8 * SPT) {
        const int oh = r0 + orow;
        float* ob = out + (size_t)img * 64 * OUT_HW * OUT_HW;
#pragma unroll
        for (int p = 0; p < 4; p++) {
            float blo = bias[oc0 + 2 * p];
            float bhi = bias[oc0 + 2 * p + 1];
#pragma unroll
            for (int t = 0; t < TN; t++) {
                int ow = ocol0 + t;
                if ((OUT_HW % TN) != 0 && ow >= OUT_HW) continue;
                float2 v = unpack2(acc[p][t]);
                ob[((size_t)(oc0 + 2 * p)     * OUT_HW + oh) * OUT_HW + ow] = fmaxf(v.x + blo, 0.f);
                ob[((size_t)(oc0 + 2 * p + 1) * OUT_HW + oh) * OUT_HW + ow] = fmaxf(v.y + bhi, 0.f);
            }
        }
    }
}

// ---------------- prototypes: segment-sum over classes / CAP(=5) ----------------
__global__ void proto_kernel(const float* __restrict__ emb_s, const int* __restrict__ y,
                             float* __restrict__ protos)
{
    int b = blockIdx.x, c = blockIdx.y;
    for (int d = threadIdx.x; d < 2304; d += blockDim.x) {
        float acc = 0.f;
#pragma unroll
        for (int s = 0; s < 25; s++) {
            if ((y[b * 25 + s] % 5) == c)
                acc += emb_s[(size_t)(b * 25 + s) * 2304 + d];
        }
        protos[(size_t)(b * 5 + c) * 2304 + d] = acc * 0.2f;
    }
}

__device__ __forceinline__ float block_reduce(float v, float* red) {
    red[threadIdx.x] = v;
    __syncthreads();
    for (int s = 128; s > 0; s >>= 1) {
        if (threadIdx.x < s) red[threadIdx.x] += red[threadIdx.x + s];
        __syncthreads();
    }
    float r = red[0];
    __syncthreads();
    return r;
}

__global__ void pnorm_kernel(const float* __restrict__ protos, float* __restrict__ pnorm) {
    __shared__ float red[256];
    const float* p = protos + (size_t)blockIdx.x * 2304;
    float s = 0.f;
    for (int d = threadIdx.x; d < 2304; d += 256) { float v = p[d]; s += v * v; }
    float tot = block_reduce(s, red);
    if (threadIdx.x == 0) pnorm[blockIdx.x] = fmaxf(sqrtf(tot), 1e-8f);
}

// ---------------- cosine-similarity logits ----------------
__global__ void logits_kernel(const float* __restrict__ emb, const float* __restrict__ protos,
                              const float* __restrict__ pnorm, float* __restrict__ out)
{
    __shared__ float red[256];
    int b = blockIdx.x / 75, t = blockIdx.x % 75;
    const float* q = emb + (size_t)(200 + b * 75 + t) * 2304;
    const float* P = protos + (size_t)b * 5 * 2304;

    float q2 = 0.f, dot[5] = {0.f, 0.f, 0.f, 0.f, 0.f};
    for (int d = threadIdx.x; d < 2304; d += 256) {
        float v = q[d];
        q2 += v * v;
#pragma unroll
        for (int c = 0; c < 5; c++) dot[c] += v * P[(size_t)c * 2304 + d];
    }
    float q2t = block_reduce(q2, red);
    float qn  = fmaxf(sqrtf(q2t), 1e-8f);
#pragma unroll
    for (int c = 0; c < 5; c++) {
        float dt = block_reduce(dot[c], red);
        if (threadIdx.x == 0)
            out[(size_t)(b * 75 + t) * 5 + c] = dt / (qn * pnorm[b * 5 + c]);
    }
}

// ---------------- launch ----------------
extern "C" void kernel_launch(void* const* d_in, const int* in_sizes, int n_in,
                              void* d_out, int out_size)
{
    const float* xs = (const float*)d_in[0];   // [8,25,3,84,84]
    const float* xt = (const float*)d_in[1];   // [8,75,3,84,84]
    const int*   y  = (const int*)  d_in[2];   // [8,25]
    const float* W1 = (const float*)d_in[3];
    const float* b1 = (const float*)d_in[4];
    const float* W2 = (const float*)d_in[5];
    const float* b2 = (const float*)d_in[6];
    const float* W3 = (const float*)d_in[7];
    const float* b3 = (const float*)d_in[8];
    const float* W4 = (const float*)d_in[9];
    const float* b4 = (const float*)d_in[10];
    float* out = (float*)d_out;

    float *act1, *act2, *act3, *emb, *w1t, *w2t, *w3t, *w4t, *protos, *pnorm;
    cudaGetSymbolAddress((void**)&act1,   g_act1);
    cudaGetSymbolAddress((void**)&act2,   g_act2);
    cudaGetSymbolAddress((void**)&act3,   g_act3);
    cudaGetSymbolAddress((void**)&emb,    g_emb);
    cudaGetSymbolAddress((void**)&w1t,    g_w1t);
    cudaGetSymbolAddress((void**)&w2t,    g_w2t);
    cudaGetSymbolAddress((void**)&w3t,    g_w3t);
    cudaGetSymbolAddress((void**)&w4t,    g_w4t);
    cudaGetSymbolAddress((void**)&protos, g_protos);
    cudaGetSymbolAddress((void**)&pnorm,  g_pnorm);

    // kernel instantiations
    auto k1 = conv_k<3,  3, 84, 42, 0, 6,  7, 6, 200, 288, 2>;
    auto k2 = conv_k<64, 4, 42, 21, 0, 7,  7, 3, 0,   192, 3>;
    auto k3 = conv_k<64, 4, 21, 11, 1, 11, 6, 2, 0,   192, 3>;
    auto k4 = conv_k<64, 4, 11, 6,  1, 6,  3, 2, 0,   96,  6>;

    // maximize smem carveout so the smem pool never clips block residency
    static int carveout_done = 0;
    if (!carveout_done) {
        cudaFuncSetAttribute((const void*)k1, cudaFuncAttributePreferredSharedMemoryCarveout, 100);
        cudaFuncSetAttribute((const void*)k2, cudaFuncAttributePreferredSharedMemoryCarveout, 100);
        cudaFuncSetAttribute((const void*)k3, cudaFuncAttributePreferredSharedMemoryCarveout, 100);
        cudaFuncSetAttribute((const void*)k4, cudaFuncAttributePreferredSharedMemoryCarveout, 100);
        carveout_done = 1;
    }

    transpose_all<<<(36864 + 255) / 256, 256>>>(W1, w1t, W2, w2t, W3, w3t, W4, w4t);

    // L1: 3->64, 84->42.  SPT=36, 8 groups -> 288 threads exactly. grid (800,7)
    k1<<<dim3(800, 7), 288>>>(xs, xt, w1t, b1, act1);
    // L2: 64->64, 42->21. SPT=21 -> 168 compute threads, padded to 192. grid (800,3)
    k2<<<dim3(800, 3), 192>>>(act1, act1, w2t, b2, act2);
    // L3: 64->64, 21->11. SPT=22 -> 176 compute threads, padded to 192. grid (800,1)
    k3<<<dim3(800, 1), 192>>>(act2, act2, w3t, b3, act3);
    // L4: 64->64, 11->6.  SPT=12 -> 96 threads exactly. grid (800,1)
    k4<<<dim3(800, 1), 96>>>(act3, act3, w4t, b4, emb);

    proto_kernel<<<dim3(8, 5), 256>>>(emb, y, protos);
    pnorm_kernel<<<40, 256>>>(protos, pnorm);
    logits_kernel<<<600, 256>>>(emb, protos, pnorm, out);
}

// round 11
// speedup vs baseline: 1.4028x; 1.2368x over previous
#include <cuda_runtime.h>
#include <cuda_bf16.h>
#include <cstdint>

typedef unsigned long long ull;

// ---------------- scratch (static device globals; no allocations) ----------------
__device__ float g_act1[800ull * 64 * 42 * 42];             // L1 out, fp32 NCHW
__device__ __nv_bfloat16 g_a1h[800ull * 42 * 42 * 64];      // NHWC bf16 hi/lo
__device__ __nv_bfloat16 g_a1l[800ull * 42 * 42 * 64];
__device__ __nv_bfloat16 g_a2h[800ull * 21 * 21 * 64];
__device__ __nv_bfloat16 g_a2l[800ull * 21 * 21 * 64];
__device__ __nv_bfloat16 g_a3h[800ull * 11 * 11 * 64];
__device__ __nv_bfloat16 g_a3l[800ull * 11 * 11 * 64];
__device__ float g_emb[800ull * 2304];                      // NHWC-flattened (head is order-invariant)
__device__ float g_w1t[3 * 9 * 64];
__device__ __nv_bfloat16 g_w2h[9 * 64 * 64], g_w2l[9 * 64 * 64];
__device__ __nv_bfloat16 g_w3h[9 * 64 * 64], g_w3l[9 * 64 * 64];
__device__ __nv_bfloat16 g_w4h[9 * 64 * 64], g_w4l[9 * 64 * 64];
__device__ float g_protos[8 * 5 * 2304];
__device__ float g_pnorm[40];

// ---------------- fp32x2 helpers (L1 SIMT kernel) ----------------
__device__ __forceinline__ void ffma2(ull &d, ull a, ull b) {
    asm("fma.rn.f32x2 %0, %1, %2, %0;" : "+l"(d) : "l"(a), "l"(b));
}
__device__ __forceinline__ ull pack2(float v) {
    ull r; asm("mov.b64 %0, {%1, %1};" : "=l"(r) : "f"(v)); return r;
}
__device__ __forceinline__ float2 unpack2(ull a) {
    float2 f; asm("mov.b64 {%0, %1}, %2;" : "=f"(f.x), "=f"(f.y) : "l"(a)); return f;
}

// ---------------- mma.sync helpers (baseline PTX, no 'a'-target needed) ----------------
#define SWZ(o) ((o) ^ (((o) >> 3) & 0x70))

__device__ __forceinline__ uint32_t smem_u32(const void* p) {
    uint32_t a;
    asm("{ .reg .u64 t; cvta.to.shared.u64 t, %1; cvt.u32.u64 %0, t; }" : "=r"(a) : "l"(p));
    return a;
}
__device__ __forceinline__ void ldsm4(uint32_t& r0, uint32_t& r1, uint32_t& r2, uint32_t& r3,
                                      uint32_t a) {
    asm volatile("ldmatrix.sync.aligned.m8n8.x4.shared.b16 {%0,%1,%2,%3}, [%4];"
                 : "=r"(r0), "=r"(r1), "=r"(r2), "=r"(r3) : "r"(a));
}
__device__ __forceinline__ void mma16816(float* c, const uint32_t* a, const uint32_t* b) {
    asm volatile(
        "mma.sync.aligned.m16n8k16.row.col.f32.bf16.bf16.f32 "
        "{%0,%1,%2,%3}, {%4,%5,%6,%7}, {%8,%9}, {%0,%1,%2,%3};"
        : "+f"(c[0]), "+f"(c[1]), "+f"(c[2]), "+f"(c[3])
        : "r"(a[0]), "r"(a[1]), "r"(a[2]), "r"(a[3]), "r"(b[0]), "r"(b[1]));
}
__device__ __forceinline__ void bf16split(float v, __nv_bfloat16& h, __nv_bfloat16& l) {
    h = __float2bfloat16(v);
    l = __float2bfloat16(v - __bfloat162float(h));
}

// ---------------- weight prep: L1 fp32 transpose + L2-4 bf16 hi/lo taps ----------------
// L2-4 layout: [tap=kh*3+kw][oc=64][ic=64]  (rows = oc, K=ic contiguous, 128B/row)
__global__ void prep_weights(const float* __restrict__ W1, const float* __restrict__ W2,
                             const float* __restrict__ W3, const float* __restrict__ W4)
{
    int i = blockIdx.x * blockDim.x + threadIdx.x;
    if (i < 1728) {
        int oc = i / 27, rem = i % 27, ic = rem / 9, k = rem % 9;
        g_w1t[(ic * 9 + k) * 64 + oc] = W1[i];
    }
    if (i < 36864) {
        int tap = i >> 12, rem = i & 4095, oc = rem >> 6, ic = rem & 63;
        int kh = tap / 3, kw = tap - kh * 3;
        int s = ((oc * 64 + ic) * 3 + kh) * 3 + kw;
        __nv_bfloat16 h, l;
        bf16split(W2[s], h, l); g_w2h[i] = h; g_w2l[i] = l;
        bf16split(W3[s], h, l); g_w3h[i] = h; g_w3l[i] = l;
        bf16split(W4[s], h, l); g_w4h[i] = h; g_w4l[i] = l;
    }
}

// ---------------- L1 SIMT conv (round-2 config; fp32 NCHW out) ----------------
template<int CIN, int ICC, int IN_HW, int OUT_HW, int PAD, int RB, int TN, int CT, int SPLIT>
__global__ void conv_k(const float* __restrict__ inA, const float* __restrict__ inB,
                       const float* __restrict__ wt,
                       const float* __restrict__ bias, float* __restrict__ out)
{
    constexpr int IN_ROWS = 2 * RB + 1;
    constexpr int W2 = IN_HW + 4;
    constexpr int SPT = RB * CT;

    __shared__ float s_in[ICC * IN_ROWS * W2];
    __shared__ __align__(16) float s_w[ICC * 9 * 64];

    const int img   = blockIdx.x;
    const int r0    = blockIdx.y * RB;
    const int tid   = threadIdx.x;
    const int ocg   = tid / SPT;
    const int spt   = tid % SPT;
    const int orow  = spt / CT;
    const int ocol0 = (spt % CT) * TN;
    const int oc0   = ocg * 8;

    ull acc[4][TN];
#pragma unroll
    for (int p = 0; p < 4; p++)
#pragma unroll
        for (int t = 0; t < TN; t++) acc[p][t] = 0ull;

    const float* inb;
    if (SPLIT && img >= SPLIT)
        inb = inB + (size_t)(img - SPLIT) * CIN * IN_HW * IN_HW;
    else
        inb = inA + (size_t)img * CIN * IN_HW * IN_HW;

    for (int ic0 = 0; ic0 < CIN; ic0 += ICC) {
        for (int i = tid; i < ICC * IN_ROWS * W2; i += blockDim.x) {
            int c   = i % W2;
            int r   = (i / W2) % IN_ROWS;
            int icc = i / (W2 * IN_ROWS);
            int gr  = 2 * r0 - PAD + r;
            int gc  = c - PAD;
            float v = 0.f;
            if ((unsigned)gr < (unsigned)IN_HW && (unsigned)gc < (unsigned)IN_HW)
                v = inb[((size_t)(ic0 + icc) * IN_HW + gr) * IN_HW + gc];
            s_in[i] = v;
        }
        for (int i = tid; i < ICC * 9 * 64; i += blockDim.x)
            s_w[i] = wt[ic0 * 9 * 64 + i];
        __syncthreads();

        for (int icc = 0; icc < ICC; icc++) {
            const float* sin = s_in + ((size_t)icc * IN_ROWS + 2 * orow) * W2 + 2 * ocol0;
            const float* sw  = s_w + icc * 576 + oc0;
#pragma unroll
            for (int kh = 0; kh < 3; kh++) {
#pragma unroll
                for (int kw = 0; kw < 3; kw++) {
                    const float* srow = sin + kh * W2 + kw;
                    const ull* wv = (const ull*)(sw + (kh * 3 + kw) * 64);
                    ull w0 = wv[0], w1 = wv[1], w2 = wv[2], w3 = wv[3];
#pragma unroll
                    for (int t = 0; t < TN; t++) {
                        ull vv = pack2(srow[2 * t]);
                        ffma2(acc[0][t], vv, w0);
                        ffma2(acc[1][t], vv, w1);
                        ffma2(acc[2][t], vv, w2);
                        ffma2(acc[3][t], vv, w3);
                    }
                }
            }
        }
        __syncthreads();
    }

    const int oh = r0 + orow;
    float* ob = out + (size_t)img * 64 * OUT_HW * OUT_HW;
#pragma unroll
    for (int p = 0; p < 4; p++) {
        float blo = bias[oc0 + 2 * p];
        float bhi = bias[oc0 + 2 * p + 1];
#pragma unroll
        for (int t = 0; t < TN; t++) {
            int ow = ocol0 + t;
            if ((OUT_HW % TN) != 0 && ow >= OUT_HW) continue;
            float2 v = unpack2(acc[p][t]);
            ob[((size_t)(oc0 + 2 * p)     * OUT_HW + oh) * OUT_HW + ow] = fmaxf(v.x + blo, 0.f);
            ob[((size_t)(oc0 + 2 * p + 1) * OUT_HW + oh) * OUT_HW + ow] = fmaxf(v.y + bhi, 0.f);
        }
    }
}

// ---------------- act1 fp32 NCHW -> bf16 hi/lo NHWC ----------------
__global__ void cvt_act1(const float* __restrict__ src,
                         __nv_bfloat16* __restrict__ dh, __nv_bfloat16* __restrict__ dl)
{
    __shared__ float t[64 * 42];
    int img = blockIdx.x, h = blockIdx.y, tid = threadIdx.x;
    const float* s = src + (size_t)img * 64 * 1764 + h * 42;
    for (int i = tid; i < 2688; i += 256) {
        int c = i / 42, w = i - c * 42;
        t[c * 42 + w] = s[(size_t)c * 1764 + w];
    }
    __syncthreads();
    size_t ob = ((size_t)img * 1764 + (size_t)h * 42) * 64;
    for (int i = tid; i < 2688; i += 256) {
        int w = i >> 6, c = i & 63;
        float v = t[c * 42 + w];
        __nv_bfloat16 hh, ll;
        bf16split(v, hh, ll);
        dh[ob + (size_t)w * 64 + c] = hh;
        dl[ob + (size_t)w * 64 + c] = ll;
    }
}

// ---------------- mma.sync implicit-GEMM conv (bf16 3-split, NHWC) ----------------
// Block: M=128 output pixels x N=64 oc. Warp w owns rows [32w, 32w+32).
// Per tap: stage A_hi/A_lo (128x64 bf16, 128B rows, swizzled) + W_hi/W_lo
// (64 oc x 64 ic), then 3 splits x 4 k-steps of m16n8k16 bf16 mma.
// B fragments use NON-transposed ldmatrix: smem tile rows are oc (=n) with k
// contiguous, so plain ldmatrix yields lane = {B[k][n], B[k+1][n]} directly.
template<int INW, int OUTW, int PAD, bool OUT_FP32>
__global__ void __launch_bounds__(128, 3)
conv_mma(const __nv_bfloat16* __restrict__ ah, const __nv_bfloat16* __restrict__ al,
         const __nv_bfloat16* __restrict__ wh, const __nv_bfloat16* __restrict__ wl,
         const float* __restrict__ bias,
         __nv_bfloat16* __restrict__ outh, __nv_bfloat16* __restrict__ outl,
         float* __restrict__ outf)
{
    constexpr int NPIX = OUTW * OUTW;

    __shared__ __align__(128) __nv_bfloat16 sAh[128 * 64];
    __shared__ __align__(128) __nv_bfloat16 sAl[128 * 64];
    __shared__ __align__(128) __nv_bfloat16 sWh[64 * 64];
    __shared__ __align__(128) __nv_bfloat16 sWl[64 * 64];

    const uint32_t AHI = smem_u32(sAh), ALO = smem_u32(sAl);
    const uint32_t WHI = smem_u32(sWh), WLO = smem_u32(sWl);

    const int tid  = threadIdx.x;
    const int lane = tid & 31, w = tid >> 5;
    const int img  = blockIdx.x;
    const int p0   = blockIdx.y * 128;

    float acc[2][8][4];
#pragma unroll
    for (int mt = 0; mt < 2; mt++)
#pragma unroll
        for (int nt = 0; nt < 8; nt++)
#pragma unroll
            for (int q = 0; q < 4; q++) acc[mt][nt][q] = 0.f;

    // ldmatrix lane->address components
    const int aRow = lane & 15;                  // A: + m0
    const int aK   = (lane & 16) ? 16 : 0;       // A: byte offset within 32B k-step
    const int bRow = (lane & 7) + ((lane & 16) ? 8 : 0);   // B: oc row within 16
    const int bK   = (lane & 8) ? 16 : 0;                  // B: k-half byte offset

    for (int tap = 0; tap < 9; ++tap) {
        const int kh = tap / 3, kw = tap - kh * 3;

        // stage: A_hi(1024) + A_lo(1024) + W_hi(512) + W_lo(512) 16B granules
        for (int i = tid; i < 3072; i += 128) {
            if (i < 2048) {
                int a = i & 1023, row = a >> 3, c = a & 7;
                uint4 v = make_uint4(0u, 0u, 0u, 0u);
                int p = p0 + row;
                if (p < NPIX) {
                    int oh = p / OUTW, ow = p - oh * OUTW;
                    int ih = 2 * oh + kh - PAD, iw = 2 * ow + kw - PAD;
                    if ((unsigned)ih < (unsigned)INW && (unsigned)iw < (unsigned)INW) {
                        const __nv_bfloat16* srcb = (i < 1024) ? ah : al;
                        v = ((const uint4*)(srcb +
                              ((size_t)img * INW * INW + (size_t)ih * INW + iw) * 64))[c];
                    }
                }
                uint32_t dst = ((i < 1024) ? AHI : ALO) + SWZ(row * 128 + c * 16);
                asm volatile("st.shared.v4.b32 [%0], {%1, %2, %3, %4};"
                             :: "r"(dst), "r"(v.x), "r"(v.y), "r"(v.z), "r"(v.w));
            } else {
                int a = i & 511, row = a >> 3, c = a & 7;
                const __nv_bfloat16* srcb = (i < 2560) ? wh : wl;
                uint4 v = ((const uint4*)(srcb + (size_t)tap * 4096 + row * 64))[c];
                uint32_t dst = ((i < 2560) ? WHI : WLO) + SWZ(row * 128 + c * 16);
                asm volatile("st.shared.v4.b32 [%0], {%1, %2, %3, %4};"
                             :: "r"(dst), "r"(v.x), "r"(v.y), "r"(v.z), "r"(v.w));
            }
        }
        __syncthreads();

#pragma unroll
        for (int s = 0; s < 3; ++s) {
            const uint32_t Ab = (s == 1) ? ALO : AHI;
            const uint32_t Bb = (s == 2) ? WLO : WHI;
#pragma unroll
            for (int ks = 0; ks < 4; ++ks) {
                const int kb = ks * 32;
                uint32_t bf[8][2];
#pragma unroll
                for (int np = 0; np < 4; ++np) {
                    uint32_t addr = Bb + SWZ((np * 16 + bRow) * 128 + kb + bK);
                    ldsm4(bf[2 * np][0], bf[2 * np][1],
                          bf[2 * np + 1][0], bf[2 * np + 1][1], addr);
                }
#pragma unroll
                for (int mt = 0; mt < 2; ++mt) {
                    uint32_t af[4];
                    uint32_t addr = Ab + SWZ((w * 32 + mt * 16 + aRow) * 128 + kb + aK);
                    ldsm4(af[0], af[1], af[2], af[3], addr);
#pragma unroll
                    for (int nt = 0; nt < 8; ++nt)
                        mma16816(acc[mt][nt], af, bf[nt]);
                }
            }
        }
        __syncthreads();
    }

    // epilogue: bias + relu; lane holds rows r, r+8 and col pairs per (mt,nt)
#pragma unroll
    for (int mt = 0; mt < 2; ++mt) {
        int r = w * 32 + mt * 16 + (lane >> 2);
#pragma unroll
        for (int half = 0; half < 2; ++half) {
            int p = p0 + r + half * 8;
            if (p >= NPIX) continue;
#pragma unroll
            for (int nt = 0; nt < 8; ++nt) {
                int col = nt * 8 + (lane & 3) * 2;
                float v0 = fmaxf(acc[mt][nt][half * 2 + 0] + bias[col],     0.f);
                float v1 = fmaxf(acc[mt][nt][half * 2 + 1] + bias[col + 1], 0.f);
                if (OUT_FP32) {
                    float2* o = (float2*)(outf + ((size_t)img * NPIX + p) * 64 + col);
                    *o = make_float2(v0, v1);
                } else {
                    __nv_bfloat16 h0, l0, h1, l1;
                    bf16split(v0, h0, l0);
                    bf16split(v1, h1, l1);
                    uint32_t hp = (uint32_t)__bfloat16_as_ushort(h0) |
                                  ((uint32_t)__bfloat16_as_ushort(h1) << 16);
                    uint32_t lp = (uint32_t)__bfloat16_as_ushort(l0) |
                                  ((uint32_t)__bfloat16_as_ushort(l1) << 16);
                    *(uint32_t*)(outh + ((size_t)img * NPIX + p) * 64 + col) = hp;
                    *(uint32_t*)(outl + ((size_t)img * NPIX + p) * 64 + col) = lp;
                }
            }
        }
    }
}

// ---------------- prototypes / norms / logits (NHWC order-invariant) ----------------
__global__ void proto_kernel(const float* __restrict__ emb_s, const int* __restrict__ y,
                             float* __restrict__ protos)
{
    int b = blockIdx.x, c = blockIdx.y;
    for (int d = threadIdx.x; d < 2304; d += blockDim.x) {
        float acc = 0.f;
#pragma unroll
        for (int s = 0; s < 25; s++) {
            if ((y[b * 25 + s] % 5) == c)
                acc += emb_s[(size_t)(b * 25 + s) * 2304 + d];
        }
        protos[(size_t)(b * 5 + c) * 2304 + d] = acc * 0.2f;
    }
}

__device__ __forceinline__ float block_reduce(float v, float* red) {
    red[threadIdx.x] = v;
    __syncthreads();
    for (int s = 128; s > 0; s >>= 1) {
        if (threadIdx.x < s) red[threadIdx.x] += red[threadIdx.x + s];
        __syncthreads();
    }
    float r = red[0];
    __syncthreads();
    return r;
}

__global__ void pnorm_kernel(const float* __restrict__ protos, float* __restrict__ pnorm) {
    __shared__ float red[256];
    const float* p = protos + (size_t)blockIdx.x * 2304;
    float s = 0.f;
    for (int d = threadIdx.x; d < 2304; d += 256) { float v = p[d]; s += v * v; }
    float tot = block_reduce(s, red);
    if (threadIdx.x == 0) pnorm[blockIdx.x] = fmaxf(sqrtf(tot), 1e-8f);
}

__global__ void logits_kernel(const float* __restrict__ emb, const float* __restrict__ protos,
                              const float* __restrict__ pnorm, float* __restrict__ out)
{
    __shared__ float red[256];
    int b = blockIdx.x / 75, t = blockIdx.x % 75;
    const float* q = emb + (size_t)(200 + b * 75 + t) * 2304;
    const float* P = protos + (size_t)b * 5 * 2304;

    float q2 = 0.f, dot[5] = {0.f, 0.f, 0.f, 0.f, 0.f};
    for (int d = threadIdx.x; d < 2304; d += 256) {
        float v = q[d];
        q2 += v * v;
#pragma unroll
        for (int c = 0; c < 5; c++) dot[c] += v * P[(size_t)c * 2304 + d];
    }
    float q2t = block_reduce(q2, red);
    float qn  = fmaxf(sqrtf(q2t), 1e-8f);
#pragma unroll
    for (int c = 0; c < 5; c++) {
        float dt = block_reduce(dot[c], red);
        if (threadIdx.x == 0)
            out[(size_t)(b * 75 + t) * 5 + c] = dt / (qn * pnorm[b * 5 + c]);
    }
}

// ---------------- launch ----------------
extern "C" void kernel_launch(void* const* d_in, const int* in_sizes, int n_in,
                              void* d_out, int out_size)
{
    const float* xs = (const float*)d_in[0];
    const float* xt = (const float*)d_in[1];
    const int*   y  = (const int*)  d_in[2];
    const float* W1 = (const float*)d_in[3];
    const float* b1 = (const float*)d_in[4];
    const float* W2 = (const float*)d_in[5];
    const float* b2 = (const float*)d_in[6];
    const float* W3 = (const float*)d_in[7];
    const float* b3 = (const float*)d_in[8];
    const float* W4 = (const float*)d_in[9];
    const float* b4 = (const float*)d_in[10];
    float* out = (float*)d_out;

    float *act1, *emb, *w1t, *protos, *pnorm;
    __nv_bfloat16 *a1h, *a1l, *a2h, *a2l, *a3h, *a3l;
    __nv_bfloat16 *w2h, *w2l, *w3h, *w3l, *w4h, *w4l;
    cudaGetSymbolAddress((void**)&act1,   g_act1);
    cudaGetSymbolAddress((void**)&a1h,    g_a1h);
    cudaGetSymbolAddress((void**)&a1l,    g_a1l);
    cudaGetSymbolAddress((void**)&a2h,    g_a2h);
    cudaGetSymbolAddress((void**)&a2l,    g_a2l);
    cudaGetSymbolAddress((void**)&a3h,    g_a3h);
    cudaGetSymbolAddress((void**)&a3l,    g_a3l);
    cudaGetSymbolAddress((void**)&emb,    g_emb);
    cudaGetSymbolAddress((void**)&w1t,    g_w1t);
    cudaGetSymbolAddress((void**)&w2h,    g_w2h);
    cudaGetSymbolAddress((void**)&w2l,    g_w2l);
    cudaGetSymbolAddress((void**)&w3h,    g_w3h);
    cudaGetSymbolAddress((void**)&w3l,    g_w3l);
    cudaGetSymbolAddress((void**)&w4h,    g_w4h);
    cudaGetSymbolAddress((void**)&w4l,    g_w4l);
    cudaGetSymbolAddress((void**)&protos, g_protos);
    cudaGetSymbolAddress((void**)&pnorm,  g_pnorm);

    prep_weights<<<(36864 + 255) / 256, 256>>>(W1, W2, W3, W4);

    // L1: SIMT fp32 conv (known-good config), NCHW out
    conv_k<3, 3, 84, 42, 0, 6, 7, 6, 200><<<dim3(800, 7), 288>>>(xs, xt, w1t, b1, act1);
    // NCHW fp32 -> NHWC bf16 hi/lo
    cvt_act1<<<dim3(800, 42), 256>>>(act1, a1h, a1l);

    // mma.sync implicit-GEMM convs (bf16 3-split)
    conv_mma<42, 21, 0, false><<<dim3(800, 4), 128>>>(a1h, a1l, w2h, w2l, b2, a2h, a2l, nullptr);
    conv_mma<21, 11, 1, false><<<dim3(800, 1), 128>>>(a2h, a2l, w3h, w3l, b3, a3h, a3l, nullptr);
    conv_mma<11, 6,  1, true ><<<dim3(800, 1), 128>>>(a3h, a3l, w4h, w4l, b4, nullptr, nullptr, emb);

    proto_kernel<<<dim3(8, 5), 256>>>(emb, y, protos);
    pnorm_kernel<<<40, 256>>>(protos, pnorm);
    logits_kernel<<<600, 256>>>(emb, protos, pnorm, out);
}

// round 12
// speedup vs baseline: 2.0345x; 1.4503x over previous
#include <cuda_runtime.h>
#include <cuda_bf16.h>
#include <cstdint>

typedef unsigned long long ull;

// ---------------- scratch (static device globals; no allocations) ----------------
__device__ float g_act1[800ull * 64 * 42 * 42];             // L1 out, fp32 NCHW
__device__ __nv_bfloat16 g_a1h[800ull * 42 * 42 * 64];      // NHWC bf16 hi/lo
__device__ __nv_bfloat16 g_a1l[800ull * 42 * 42 * 64];
__device__ __nv_bfloat16 g_a2h[800ull * 21 * 21 * 64];
__device__ __nv_bfloat16 g_a2l[800ull * 21 * 21 * 64];
__device__ __nv_bfloat16 g_a3h[800ull * 11 * 11 * 64];
__device__ __nv_bfloat16 g_a3l[800ull * 11 * 11 * 64];
__device__ float g_emb[800ull * 2304];                      // NHWC-flattened (head is order-invariant)
__device__ float g_w1t[3 * 9 * 64];
__device__ __nv_bfloat16 g_w2h[9 * 64 * 64], g_w2l[9 * 64 * 64];
__device__ __nv_bfloat16 g_w3h[9 * 64 * 64], g_w3l[9 * 64 * 64];
__device__ __nv_bfloat16 g_w4h[9 * 64 * 64], g_w4l[9 * 64 * 64];
__device__ float g_protos[8 * 5 * 2304];
__device__ float g_pnorm[40];

// ---------------- fp32x2 helpers (L1 SIMT kernel) ----------------
__device__ __forceinline__ void ffma2(ull &d, ull a, ull b) {
    asm("fma.rn.f32x2 %0, %1, %2, %0;" : "+l"(d) : "l"(a), "l"(b));
}
__device__ __forceinline__ ull pack2(float v) {
    ull r; asm("mov.b64 %0, {%1, %1};" : "=l"(r) : "f"(v)); return r;
}
__device__ __forceinline__ float2 unpack2(ull a) {
    float2 f; asm("mov.b64 {%0, %1}, %2;" : "=f"(f.x), "=f"(f.y) : "l"(a)); return f;
}

// ---------------- mma.sync helpers (baseline PTX, no 'a'-target needed) ----------------
#define SWZ(o) ((o) ^ (((o) >> 3) & 0x70))

__device__ __forceinline__ uint32_t smem_u32(const void* p) {
    uint32_t a;
    asm("{ .reg .u64 t; cvta.to.shared.u64 t, %1; cvt.u32.u64 %0, t; }" : "=r"(a) : "l"(p));
    return a;
}
__device__ __forceinline__ void ldsm4(uint32_t& r0, uint32_t& r1, uint32_t& r2, uint32_t& r3,
                                      uint32_t a) {
    asm volatile("ldmatrix.sync.aligned.m8n8.x4.shared.b16 {%0,%1,%2,%3}, [%4];"
                 : "=r"(r0), "=r"(r1), "=r"(r2), "=r"(r3) : "r"(a));
}
__device__ __forceinline__ void mma16816(float* c, const uint32_t* a, const uint32_t* b) {
    asm volatile(
        "mma.sync.aligned.m16n8k16.row.col.f32.bf16.bf16.f32 "
        "{%0,%1,%2,%3}, {%4,%5,%6,%7}, {%8,%9}, {%0,%1,%2,%3};"
        : "+f"(c[0]), "+f"(c[1]), "+f"(c[2]), "+f"(c[3])
        : "r"(a[0]), "r"(a[1]), "r"(a[2]), "r"(a[3]), "r"(b[0]), "r"(b[1]));
}
__device__ __forceinline__ void cpasync16(uint32_t dst, const void* src, uint32_t ssz) {
    asm volatile("cp.async.cg.shared.global [%0], [%1], 16, %2;"
                 :: "r"(dst), "l"(src), "r"(ssz));
}
__device__ __forceinline__ void bf16split(float v, __nv_bfloat16& h, __nv_bfloat16& l) {
    h = __float2bfloat16(v);
    l = __float2bfloat16(v - __bfloat162float(h));
}

// ---------------- weight prep: L1 fp32 transpose + L2-4 bf16 hi/lo taps ----------------
// L2-4 layout: [tap=kh*3+kw][oc=64][ic=64]  (rows = oc, K=ic contiguous, 128B/row)
__global__ void prep_weights(const float* __restrict__ W1, const float* __restrict__ W2,
                             const float* __restrict__ W3, const float* __restrict__ W4)
{
    int i = blockIdx.x * blockDim.x + threadIdx.x;
    if (i < 1728) {
        int oc = i / 27, rem = i % 27, ic = rem / 9, k = rem % 9;
        g_w1t[(ic * 9 + k) * 64 + oc] = W1[i];
    }
    if (i < 36864) {
        int tap = i >> 12, rem = i & 4095, oc = rem >> 6, ic = rem & 63;
        int kh = tap / 3, kw = tap - kh * 3;
        int s = ((oc * 64 + ic) * 3 + kh) * 3 + kw;
        __nv_bfloat16 h, l;
        bf16split(W2[s], h, l); g_w2h[i] = h; g_w2l[i] = l;
        bf16split(W3[s], h, l); g_w3h[i] = h; g_w3l[i] = l;
        bf16split(W4[s], h, l); g_w4h[i] = h; g_w4l[i] = l;
    }
}

// ---------------- L1 SIMT conv (round-2 config; fp32 NCHW out) ----------------
template<int CIN, int ICC, int IN_HW, int OUT_HW, int PAD, int RB, int TN, int CT, int SPLIT>
__global__ void conv_k(const float* __restrict__ inA, const float* __restrict__ inB,
                       const float* __restrict__ wt,
                       const float* __restrict__ bias, float* __restrict__ out)
{
    constexpr int IN_ROWS = 2 * RB + 1;
    constexpr int W2 = IN_HW + 4;
    constexpr int SPT = RB * CT;

    __shared__ float s_in[ICC * IN_ROWS * W2];
    __shared__ __align__(16) float s_w[ICC * 9 * 64];

    const int img   = blockIdx.x;
    const int r0    = blockIdx.y * RB;
    const int tid   = threadIdx.x;
    const int ocg   = tid / SPT;
    const int spt   = tid % SPT;
    const int orow  = spt / CT;
    const int ocol0 = (spt % CT) * TN;
    const int oc0   = ocg * 8;

    ull acc[4][TN];
#pragma unroll
    for (int p = 0; p < 4; p++)
#pragma unroll
        for (int t = 0; t < TN; t++) acc[p][t] = 0ull;

    const float* inb;
    if (SPLIT && img >= SPLIT)
        inb = inB + (size_t)(img - SPLIT) * CIN * IN_HW * IN_HW;
    else
        inb = inA + (size_t)img * CIN * IN_HW * IN_HW;

    for (int ic0 = 0; ic0 < CIN; ic0 += ICC) {
        for (int i = tid; i < ICC * IN_ROWS * W2; i += blockDim.x) {
            int c   = i % W2;
            int r   = (i / W2) % IN_ROWS;
            int icc = i / (W2 * IN_ROWS);
            int gr  = 2 * r0 - PAD + r;
            int gc  = c - PAD;
            float v = 0.f;
            if ((unsigned)gr < (unsigned)IN_HW && (unsigned)gc < (unsigned)IN_HW)
                v = inb[((size_t)(ic0 + icc) * IN_HW + gr) * IN_HW + gc];
            s_in[i] = v;
        }
        for (int i = tid; i < ICC * 9 * 64; i += blockDim.x)
            s_w[i] = wt[ic0 * 9 * 64 + i];
        __syncthreads();

        for (int icc = 0; icc < ICC; icc++) {
            const float* sin = s_in + ((size_t)icc * IN_ROWS + 2 * orow) * W2 + 2 * ocol0;
            const float* sw  = s_w + icc * 576 + oc0;
#pragma unroll
            for (int kh = 0; kh < 3; kh++) {
#pragma unroll
                for (int kw = 0; kw < 3; kw++) {
                    const float* srow = sin + kh * W2 + kw;
                    const ull* wv = (const ull*)(sw + (kh * 3 + kw) * 64);
                    ull w0 = wv[0], w1 = wv[1], w2 = wv[2], w3 = wv[3];
#pragma unroll
                    for (int t = 0; t < TN; t++) {
                        ull vv = pack2(srow[2 * t]);
                        ffma2(acc[0][t], vv, w0);
                        ffma2(acc[1][t], vv, w1);
                        ffma2(acc[2][t], vv, w2);
                        ffma2(acc[3][t], vv, w3);
                    }
                }
            }
        }
        __syncthreads();
    }

    const int oh = r0 + orow;
    float* ob = out + (size_t)img * 64 * OUT_HW * OUT_HW;
#pragma unroll
    for (int p = 0; p < 4; p++) {
        float blo = bias[oc0 + 2 * p];
        float bhi = bias[oc0 + 2 * p + 1];
#pragma unroll
        for (int t = 0; t < TN; t++) {
            int ow = ocol0 + t;
            if ((OUT_HW % TN) != 0 && ow >= OUT_HW) continue;
            float2 v = unpack2(acc[p][t]);
            ob[((size_t)(oc0 + 2 * p)     * OUT_HW + oh) * OUT_HW + ow] = fmaxf(v.x + blo, 0.f);
            ob[((size_t)(oc0 + 2 * p + 1) * OUT_HW + oh) * OUT_HW + ow] = fmaxf(v.y + bhi, 0.f);
        }
    }
}

// ---------------- act1 fp32 NCHW -> bf16 hi/lo NHWC ----------------
__global__ void cvt_act1(const float* __restrict__ src,
                         __nv_bfloat16* __restrict__ dh, __nv_bfloat16* __restrict__ dl)
{
    __shared__ float t[64 * 42];
    int img = blockIdx.x, h = blockIdx.y, tid = threadIdx.x;
    const float* s = src + (size_t)img * 64 * 1764 + h * 42;
    for (int i = tid; i < 2688; i += 256) {
        int c = i / 42, w = i - c * 42;
        t[c * 42 + w] = s[(size_t)c * 1764 + w];
    }
    __syncthreads();
    size_t ob = ((size_t)img * 1764 + (size_t)h * 42) * 64;
    for (int i = tid; i < 2688; i += 256) {
        int w = i >> 6, c = i & 63;
        float v = t[c * 42 + w];
        __nv_bfloat16 hh, ll;
        bf16split(v, hh, ll);
        dh[ob + (size_t)w * 64 + c] = hh;
        dl[ob + (size_t)w * 64 + c] = ll;
    }
}

// ---------------- mma.sync implicit-GEMM conv, cp.async double-buffered ----------------
// Block: M=128 output pixels x N=64 oc. Warp w owns rows [32w, 32w+32).
// Tap t+1's A/W tiles stream in via cp.async while tap t's MMAs run.
// Dynamic smem (96KB + align pad): AH[2],AL[2] 16KB each; WH[2],WL[2] 8KB each.
template<int INW, int OUTW, int PAD, bool OUT_FP32>
__global__ void __launch_bounds__(128)
conv_mma(const __nv_bfloat16* __restrict__ ah, const __nv_bfloat16* __restrict__ al,
         const __nv_bfloat16* __restrict__ wh, const __nv_bfloat16* __restrict__ wl,
         const float* __restrict__ bias,
         __nv_bfloat16* __restrict__ outh, __nv_bfloat16* __restrict__ outl,
         float* __restrict__ outf)
{
    constexpr int NPIX = OUTW * OUTW;

    extern __shared__ char dsm[];
    const uint32_t base = (smem_u32(dsm) + 1023) & ~1023u;
    const uint32_t AH = base, AL = base + 32768, WH = base + 65536, WL = base + 81920;

    const int tid  = threadIdx.x;
    const int lane = tid & 31, w = tid >> 5;
    const int img  = blockIdx.x;
    const int p0   = blockIdx.y * 128;

    // per-thread staging coords (thread stages A row `tid`, W row tid>>1)
    const int  p   = p0 + tid;
    const bool pv  = p < NPIX;
    const int  pc  = pv ? p : 0;
    const int  oh2 = 2 * (pc / OUTW) - PAD;
    const int  ow2 = 2 * (pc % OUTW) - PAD;
    const size_t imgbase = (size_t)img * INW * INW * 64;
    const int  wrow = tid >> 1, wc0 = (tid & 1) * 4;

    auto stage = [&](int tap, int sel) {
        const int kh = tap / 3, kw = tap - kh * 3;
        const int ih = oh2 + kh, iw = ow2 + kw;
        const bool valid = pv && (unsigned)ih < (unsigned)INW && (unsigned)iw < (unsigned)INW;
        const uint32_t ssz = valid ? 16u : 0u;
        const size_t off = valid ? (imgbase + ((size_t)ih * INW + iw) * 64) : imgbase;
        const __nv_bfloat16* sh_ = ah + off;
        const __nv_bfloat16* sl_ = al + off;
        const uint32_t dh_ = AH + sel * 16384;
        const uint32_t dl_ = AL + sel * 16384;
#pragma unroll
        for (int c = 0; c < 8; c++) {
            uint32_t d = SWZ(tid * 128 + c * 16);
            cpasync16(dh_ + d, sh_ + c * 8, ssz);
            cpasync16(dl_ + d, sl_ + c * 8, ssz);
        }
        const __nv_bfloat16* wsh = wh + tap * 4096 + wrow * 64 + wc0 * 8;
        const __nv_bfloat16* wsl = wl + tap * 4096 + wrow * 64 + wc0 * 8;
        const uint32_t dwh = WH + sel * 8192, dwl = WL + sel * 8192;
#pragma unroll
        for (int c = 0; c < 4; c++) {
            uint32_t d = SWZ(wrow * 128 + (wc0 + c) * 16);
            cpasync16(dwh + d, wsh + c * 8, 16u);
            cpasync16(dwl + d, wsl + c * 8, 16u);
        }
    };

    float acc[2][8][4];
#pragma unroll
    for (int mt = 0; mt < 2; mt++)
#pragma unroll
        for (int nt = 0; nt < 8; nt++)
#pragma unroll
            for (int q = 0; q < 4; q++) acc[mt][nt][q] = 0.f;

    // ldmatrix lane->address components
    const int aRow = lane & 15;
    const int aK   = (lane & 16) ? 16 : 0;
    const int bRow = (lane & 7) + ((lane & 16) ? 8 : 0);
    const int bK   = (lane & 8) ? 16 : 0;

    stage(0, 0);
    asm volatile("cp.async.commit_group;" ::: "memory");

    for (int tap = 0; tap < 9; ++tap) {
        const int sel = tap & 1;
        if (tap < 8) {
            stage(tap + 1, sel ^ 1);
            asm volatile("cp.async.commit_group;" ::: "memory");
            asm volatile("cp.async.wait_group 1;" ::: "memory");
        } else {
            asm volatile("cp.async.wait_group 0;" ::: "memory");
        }
        __syncthreads();

        const uint32_t Asel = sel * 16384, Wsel = sel * 8192;
#pragma unroll
        for (int s = 0; s < 3; ++s) {
            const uint32_t Ab = ((s == 1) ? AL : AH) + Asel;
            const uint32_t Bb = ((s == 2) ? WL : WH) + Wsel;
#pragma unroll
            for (int ks = 0; ks < 4; ++ks) {
                const int kb = ks * 32;
                uint32_t bf[8][2];
#pragma unroll
                for (int np = 0; np < 4; ++np) {
                    uint32_t addr = Bb + SWZ((np * 16 + bRow) * 128 + kb + bK);
                    ldsm4(bf[2 * np][0], bf[2 * np][1],
                          bf[2 * np + 1][0], bf[2 * np + 1][1], addr);
                }
#pragma unroll
                for (int mt = 0; mt < 2; ++mt) {
                    uint32_t af[4];
                    uint32_t addr = Ab + SWZ((w * 32 + mt * 16 + aRow) * 128 + kb + aK);
                    ldsm4(af[0], af[1], af[2], af[3], addr);
#pragma unroll
                    for (int nt = 0; nt < 8; ++nt)
                        mma16816(acc[mt][nt], af, bf[nt]);
                }
            }
        }
        __syncthreads();
    }

    // epilogue: bias + relu; lane holds rows r, r+8 and col pairs per (mt,nt)
#pragma unroll
    for (int mt = 0; mt < 2; ++mt) {
        int r = w * 32 + mt * 16 + (lane >> 2);
#pragma unroll
        for (int half = 0; half < 2; ++half) {
            int pp = p0 + r + half * 8;
            if (pp >= NPIX) continue;
#pragma unroll
            for (int nt = 0; nt < 8; ++nt) {
                int col = nt * 8 + (lane & 3) * 2;
                float v0 = fmaxf(acc[mt][nt][half * 2 + 0] + bias[col],     0.f);
                float v1 = fmaxf(acc[mt][nt][half * 2 + 1] + bias[col + 1], 0.f);
                if (OUT_FP32) {
                    float2* o = (float2*)(outf + ((size_t)img * NPIX + pp) * 64 + col);
                    *o = make_float2(v0, v1);
                } else {
                    __nv_bfloat16 h0, l0, h1, l1;
                    bf16split(v0, h0, l0);
                    bf16split(v1, h1, l1);
                    uint32_t hp = (uint32_t)__bfloat16_as_ushort(h0) |
                                  ((uint32_t)__bfloat16_as_ushort(h1) << 16);
                    uint32_t lp = (uint32_t)__bfloat16_as_ushort(l0) |
                                  ((uint32_t)__bfloat16_as_ushort(l1) << 16);
                    *(uint32_t*)(outh + ((size_t)img * NPIX + pp) * 64 + col) = hp;
                    *(uint32_t*)(outl + ((size_t)img * NPIX + pp) * 64 + col) = lp;
                }
            }
        }
    }
}

// ---------------- prototypes / norms / logits (NHWC order-invariant) ----------------
__global__ void proto_kernel(const float* __restrict__ emb_s, const int* __restrict__ y,
                             float* __restrict__ protos)
{
    int b = blockIdx.x, c = blockIdx.y;
    for (int d = threadIdx.x; d < 2304; d += blockDim.x) {
        float acc = 0.f;
#pragma unroll
        for (int s = 0; s < 25; s++) {
            if ((y[b * 25 + s] % 5) == c)
                acc += emb_s[(size_t)(b * 25 + s) * 2304 + d];
        }
        protos[(size_t)(b * 5 + c) * 2304 + d] = acc * 0.2f;
    }
}

__device__ __forceinline__ float block_reduce(float v, float* red) {
    red[threadIdx.x] = v;
    __syncthreads();
    for (int s = 128; s > 0; s >>= 1) {
        if (threadIdx.x < s) red[threadIdx.x] += red[threadIdx.x + s];
        __syncthreads();
    }
    float r = red[0];
    __syncthreads();
    return r;
}

__global__ void pnorm_kernel(const float* __restrict__ protos, float* __restrict__ pnorm) {
    __shared__ float red[256];
    const float* p = protos + (size_t)blockIdx.x * 2304;
    float s = 0.f;
    for (int d = threadIdx.x; d < 2304; d += 256) { float v = p[d]; s += v * v; }
    float tot = block_reduce(s, red);
    if (threadIdx.x == 0) pnorm[blockIdx.x] = fmaxf(sqrtf(tot), 1e-8f);
}

__global__ void logits_kernel(const float* __restrict__ emb, const float* __restrict__ protos,
                              const float* __restrict__ pnorm, float* __restrict__ out)
{
    __shared__ float red[256];
    int b = blockIdx.x / 75, t = blockIdx.x % 75;
    const float* q = emb + (size_t)(200 + b * 75 + t) * 2304;
    const float* P = protos + (size_t)b * 5 * 2304;

    float q2 = 0.f, dot[5] = {0.f, 0.f, 0.f, 0.f, 0.f};
    for (int d = threadIdx.x; d < 2304; d += 256) {
        float v = q[d];
        q2 += v * v;
#pragma unroll
        for (int c = 0; c < 5; c++) dot[c] += v * P[(size_t)c * 2304 + d];
    }
    float q2t = block_reduce(q2, red);
    float qn  = fmaxf(sqrtf(q2t), 1e-8f);
#pragma unroll
    for (int c = 0; c < 5; c++) {
        float dt = block_reduce(dot[c], red);
        if (threadIdx.x == 0)
            out[(size_t)(b * 75 + t) * 5 + c] = dt / (qn * pnorm[b * 5 + c]);
    }
}

// ---------------- launch ----------------
extern "C" void kernel_launch(void* const* d_in, const int* in_sizes, int n_in,
                              void* d_out, int out_size)
{
    const float* xs = (const float*)d_in[0];
    const float* xt = (const float*)d_in[1];
    const int*   y  = (const int*)  d_in[2];
    const float* W1 = (const float*)d_in[3];
    const float* b1 = (const float*)d_in[4];
    const float* W2 = (const float*)d_in[5];
    const float* b2 = (const float*)d_in[6];
    const float* W3 = (const float*)d_in[7];
    const float* b3 = (const float*)d_in[8];
    const float* W4 = (const float*)d_in[9];
    const float* b4 = (const float*)d_in[10];
    float* out = (float*)d_out;

    float *act1, *emb, *w1t, *protos, *pnorm;
    __nv_bfloat16 *a1h, *a1l, *a2h, *a2l, *a3h, *a3l;
    __nv_bfloat16 *w2h, *w2l, *w3h, *w3l, *w4h, *w4l;
    cudaGetSymbolAddress((void**)&act1,   g_act1);
    cudaGetSymbolAddress((void**)&a1h,    g_a1h);
    cudaGetSymbolAddress((void**)&a1l,    g_a1l);
    cudaGetSymbolAddress((void**)&a2h,    g_a2h);
    cudaGetSymbolAddress((void**)&a2l,    g_a2l);
    cudaGetSymbolAddress((void**)&a3h,    g_a3h);
    cudaGetSymbolAddress((void**)&a3l,    g_a3l);
    cudaGetSymbolAddress((void**)&emb,    g_emb);
    cudaGetSymbolAddress((void**)&w1t,    g_w1t);
    cudaGetSymbolAddress((void**)&w2h,    g_w2h);
    cudaGetSymbolAddress((void**)&w2l,    g_w2l);
    cudaGetSymbolAddress((void**)&w3h,    g_w3h);
    cudaGetSymbolAddress((void**)&w3l,    g_w3l);
    cudaGetSymbolAddress((void**)&w4h,    g_w4h);
    cudaGetSymbolAddress((void**)&w4l,    g_w4l);
    cudaGetSymbolAddress((void**)&protos, g_protos);
    cudaGetSymbolAddress((void**)&pnorm,  g_pnorm);

    auto c2 = conv_mma<42, 21, 0, false>;
    auto c3 = conv_mma<21, 11, 1, false>;
    auto c4 = conv_mma<11, 6,  1, true>;
    const int DSMEM = 98304 + 1024;
    static int attr_done = 0;
    if (!attr_done) {
        cudaFuncSetAttribute((const void*)c2, cudaFuncAttributeMaxDynamicSharedMemorySize, DSMEM);
        cudaFuncSetAttribute((const void*)c3, cudaFuncAttributeMaxDynamicSharedMemorySize, DSMEM);
        cudaFuncSetAttribute((const void*)c4, cudaFuncAttributeMaxDynamicSharedMemorySize, DSMEM);
        attr_done = 1;
    }

    prep_weights<<<(36864 + 255) / 256, 256>>>(W1, W2, W3, W4);

    // L1: SIMT fp32 conv (known-good config), NCHW out
    conv_k<3, 3, 84, 42, 0, 6, 7, 6, 200><<<dim3(800, 7), 288>>>(xs, xt, w1t, b1, act1);
    // NCHW fp32 -> NHWC bf16 hi/lo
    cvt_act1<<<dim3(800, 42), 256>>>(act1, a1h, a1l);

    // mma.sync implicit-GEMM convs (bf16 3-split, cp.async pipelined)
    c2<<<dim3(800, 4), 128, DSMEM>>>(a1h, a1l, w2h, w2l, b2, a2h, a2l, nullptr);
    c3<<<dim3(800, 1), 128, DSMEM>>>(a2h, a2l, w3h, w3l, b3, a3h, a3l, nullptr);
    c4<<<dim3(800, 1), 128, DSMEM>>>(a3h, a3l, w4h, w4l, b4, nullptr, nullptr, emb);

    proto_kernel<<<dim3(8, 5), 256>>>(emb, y, protos);
    pnorm_kernel<<<40, 256>>>(protos, pnorm);
    logits_kernel<<<600, 256>>>(emb, protos, pnorm, out);
}

// round 13
// speedup vs baseline: 3.2818x; 1.6130x over previous
#include <cuda_runtime.h>
#include <cuda_bf16.h>
#include <cstdint>

typedef unsigned long long ull;

// ---------------- scratch (static device globals; no allocations) ----------------
__device__ __nv_bfloat16 g_a1h[800ull * 42 * 42 * 64];      // NHWC bf16 hi/lo
__device__ __nv_bfloat16 g_a1l[800ull * 42 * 42 * 64];
__device__ __nv_bfloat16 g_a2h[800ull * 21 * 21 * 64];
__device__ __nv_bfloat16 g_a2l[800ull * 21 * 21 * 64];
__device__ __nv_bfloat16 g_a3h[800ull * 11 * 11 * 64];
__device__ __nv_bfloat16 g_a3l[800ull * 11 * 11 * 64];
__device__ float g_emb[800ull * 2304];                      // NHWC-flattened (head is order-invariant)
__device__ __nv_bfloat16 g_w1h[64 * 32], g_w1l[64 * 32];    // L1: [oc][k=tap*3+ch, pad 32]
__device__ __nv_bfloat16 g_w2h[9 * 64 * 64], g_w2l[9 * 64 * 64];
__device__ __nv_bfloat16 g_w3h[9 * 64 * 64], g_w3l[9 * 64 * 64];
__device__ __nv_bfloat16 g_w4h[9 * 64 * 64], g_w4l[9 * 64 * 64];
__device__ float g_protos[8 * 5 * 2304];
__device__ float g_pnorm[40];

// ---------------- mma.sync helpers (baseline PTX, no 'a'-target needed) ----------------
#define SWZ(o) ((o) ^ (((o) >> 3) & 0x70))

__device__ __forceinline__ uint32_t smem_u32(const void* p) {
    uint32_t a;
    asm("{ .reg .u64 t; cvta.to.shared.u64 t, %1; cvt.u32.u64 %0, t; }" : "=r"(a) : "l"(p));
    return a;
}
__device__ __forceinline__ void ldsm4(uint32_t& r0, uint32_t& r1, uint32_t& r2, uint32_t& r3,
                                      uint32_t a) {
    asm volatile("ldmatrix.sync.aligned.m8n8.x4.shared.b16 {%0,%1,%2,%3}, [%4];"
                 : "=r"(r0), "=r"(r1), "=r"(r2), "=r"(r3) : "r"(a));
}
__device__ __forceinline__ void mma16816(float* c, const uint32_t* a, const uint32_t* b) {
    asm volatile(
        "mma.sync.aligned.m16n8k16.row.col.f32.bf16.bf16.f32 "
        "{%0,%1,%2,%3}, {%4,%5,%6,%7}, {%8,%9}, {%0,%1,%2,%3};"
        : "+f"(c[0]), "+f"(c[1]), "+f"(c[2]), "+f"(c[3])
        : "r"(a[0]), "r"(a[1]), "r"(a[2]), "r"(a[3]), "r"(b[0]), "r"(b[1]));
}
__device__ __forceinline__ void cpasync16(uint32_t dst, const void* src, uint32_t ssz) {
    asm volatile("cp.async.cg.shared.global [%0], [%1], 16, %2;"
                 :: "r"(dst), "l"(src), "r"(ssz));
}
__device__ __forceinline__ void bf16split(float v, __nv_bfloat16& h, __nv_bfloat16& l) {
    h = __float2bfloat16(v);
    l = __float2bfloat16(v - __bfloat162float(h));
}

// ---------------- weight prep: all layers bf16 hi/lo ----------------
// L1: [oc=64][k=32] with k = (kh*3+kw)*3 + ic (cols 27-31 zero)
// L2-4: [tap=kh*3+kw][oc=64][ic=64]
__global__ void prep_weights(const float* __restrict__ W1, const float* __restrict__ W2,
                             const float* __restrict__ W3, const float* __restrict__ W4)
{
    int i = blockIdx.x * blockDim.x + threadIdx.x;
    if (i < 2048) {
        int oc = i >> 5, k = i & 31;
        float v = 0.f;
        if (k < 27) {
            int t = k / 3, c = k - 3 * t;       // t = kh*3+kw, c = ic
            v = W1[oc * 27 + c * 9 + t];
        }
        __nv_bfloat16 h, l;
        bf16split(v, h, l);
        g_w1h[i] = h; g_w1l[i] = l;
    }
    if (i < 36864) {
        int tap = i >> 12, rem = i & 4095, oc = rem >> 6, ic = rem & 63;
        int kh = tap / 3, kw = tap - kh * 3;
        int s = ((oc * 64 + ic) * 3 + kh) * 3 + kw;
        __nv_bfloat16 h, l;
        bf16split(W2[s], h, l); g_w2h[i] = h; g_w2l[i] = l;
        bf16split(W3[s], h, l); g_w3h[i] = h; g_w3l[i] = l;
        bf16split(W4[s], h, l); g_w4h[i] = h; g_w4l[i] = l;
    }
}

// ---------------- L1 as one GEMM: M=128 pixels x N=64 oc x K=32 (27 used) ----------------
// A row = output pixel; col k = tap*3+ch gathered from fp32 NCHW input.
// Writes NHWC bf16 hi/lo directly (no fp32 intermediate, no cvt pass).
__global__ void __launch_bounds__(128)
conv1_mma(const float* __restrict__ xs, const float* __restrict__ xt,
          const __nv_bfloat16* __restrict__ w1h, const __nv_bfloat16* __restrict__ w1l,
          const float* __restrict__ bias,
          __nv_bfloat16* __restrict__ outh, __nv_bfloat16* __restrict__ outl)
{
    constexpr int NPIX = 42 * 42;   // 1764

    __shared__ __align__(128) __nv_bfloat16 sAh[128 * 64];  // 128 rows x 128B (cols 0-31 used)
    __shared__ __align__(128) __nv_bfloat16 sAl[128 * 64];
    __shared__ __align__(128) __nv_bfloat16 sWh[64 * 64];   // 64 rows x 128B (cols 0-31 used)
    __shared__ __align__(128) __nv_bfloat16 sWl[64 * 64];

    const uint32_t AH = smem_u32(sAh), AL = smem_u32(sAl);
    const uint32_t WH = smem_u32(sWh), WL = smem_u32(sWl);

    const int tid  = threadIdx.x;
    const int lane = tid & 31, w = tid >> 5;
    const int img  = blockIdx.x;
    const int p0   = blockIdx.y * 128;

    // ---- stage A: thread tid owns pixel row tid ----
    {
        const int p  = p0 + tid;
        const bool pv = p < NPIX;
        const int pc = pv ? p : 0;
        const int oh2 = 2 * (pc / 42), ow2 = 2 * (pc % 42);   // PAD=0
        const float* x = (img < 200) ? (xs + (size_t)img * 3 * 7056)
                                     : (xt + (size_t)(img - 200) * 3 * 7056);
#pragma unroll
        for (int k = 0; k < 32; k++) {
            float v = 0.f;
            if (k < 27 && pv) {
                int t = k / 3, c = k - 3 * t;
                int ih = oh2 + t / 3, iw = ow2 + t % 3;
                if (ih < 84 && iw < 84)
                    v = x[(size_t)c * 7056 + ih * 84 + iw];
            }
            __nv_bfloat16 h, l;
            bf16split(v, h, l);
            uint32_t d = SWZ(tid * 128 + (k >> 3) * 16) + (k & 7) * 2;
            asm volatile("st.shared.b16 [%0], %1;" :: "r"(AH + d), "h"(__bfloat16_as_ushort(h)));
            asm volatile("st.shared.b16 [%0], %1;" :: "r"(AL + d), "h"(__bfloat16_as_ushort(l)));
        }
    }
    // ---- stage W: 64 rows x 4 granules x 2 tensors = 512 granules ----
    for (int i = tid; i < 512; i += 128) {
        int j = i & 255, row = j >> 2, g = j & 3;
        const __nv_bfloat16* src = (i < 256) ? w1h : w1l;
        uint4 v = *(const uint4*)(src + row * 32 + g * 8);
        uint32_t dst = ((i < 256) ? WH : WL) + SWZ(row * 128 + g * 16);
        asm volatile("st.shared.v4.b32 [%0], {%1, %2, %3, %4};"
                     :: "r"(dst), "r"(v.x), "r"(v.y), "r"(v.z), "r"(v.w));
    }
    __syncthreads();

    float acc[2][8][4];
#pragma unroll
    for (int mt = 0; mt < 2; mt++)
#pragma unroll
        for (int nt = 0; nt < 8; nt++)
#pragma unroll
            for (int q = 0; q < 4; q++) acc[mt][nt][q] = 0.f;

    const int aRow = lane & 15;
    const int aK   = (lane & 16) ? 16 : 0;
    const int bRow = (lane & 7) + ((lane & 16) ? 8 : 0);
    const int bK   = (lane & 8) ? 16 : 0;

#pragma unroll
    for (int s = 0; s < 3; ++s) {
        const uint32_t Ab = (s == 1) ? AL : AH;
        const uint32_t Bb = (s == 2) ? WL : WH;
#pragma unroll
        for (int ks = 0; ks < 2; ++ks) {
            const int kb = ks * 32;
            uint32_t bf[8][2];
#pragma unroll
            for (int np = 0; np < 4; ++np) {
                uint32_t addr = Bb + SWZ((np * 16 + bRow) * 128 + kb + bK);
                ldsm4(bf[2 * np][0], bf[2 * np][1],
                      bf[2 * np + 1][0], bf[2 * np + 1][1], addr);
            }
#pragma unroll
            for (int mt = 0; mt < 2; ++mt) {
                uint32_t af[4];
                uint32_t addr = Ab + SWZ((w * 32 + mt * 16 + aRow) * 128 + kb + aK);
                ldsm4(af[0], af[1], af[2], af[3], addr);
#pragma unroll
                for (int nt = 0; nt < 8; ++nt)
                    mma16816(acc[mt][nt], af, bf[nt]);
            }
        }
    }

    // epilogue: bias + relu -> NHWC bf16 hi/lo
#pragma unroll
    for (int mt = 0; mt < 2; ++mt) {
        int r = w * 32 + mt * 16 + (lane >> 2);
#pragma unroll
        for (int half = 0; half < 2; ++half) {
            int pp = p0 + r + half * 8;
            if (pp >= NPIX) continue;
#pragma unroll
            for (int nt = 0; nt < 8; ++nt) {
                int col = nt * 8 + (lane & 3) * 2;
                float v0 = fmaxf(acc[mt][nt][half * 2 + 0] + bias[col],     0.f);
                float v1 = fmaxf(acc[mt][nt][half * 2 + 1] + bias[col + 1], 0.f);
                __nv_bfloat16 h0, l0, h1, l1;
                bf16split(v0, h0, l0);
                bf16split(v1, h1, l1);
                uint32_t hp = (uint32_t)__bfloat16_as_ushort(h0) |
                              ((uint32_t)__bfloat16_as_ushort(h1) << 16);
                uint32_t lp = (uint32_t)__bfloat16_as_ushort(l0) |
                              ((uint32_t)__bfloat16_as_ushort(l1) << 16);
                *(uint32_t*)(outh + ((size_t)img * NPIX + pp) * 64 + col) = hp;
                *(uint32_t*)(outl + ((size_t)img * NPIX + pp) * 64 + col) = lp;
            }
        }
    }
}

// ---------------- mma.sync implicit-GEMM conv, cp.async double-buffered (L2-L4) ----------------
template<int INW, int OUTW, int PAD, bool OUT_FP32>
__global__ void __launch_bounds__(128)
conv_mma(const __nv_bfloat16* __restrict__ ah, const __nv_bfloat16* __restrict__ al,
         const __nv_bfloat16* __restrict__ wh, const __nv_bfloat16* __restrict__ wl,
         const float* __restrict__ bias,
         __nv_bfloat16* __restrict__ outh, __nv_bfloat16* __restrict__ outl,
         float* __restrict__ outf)
{
    constexpr int NPIX = OUTW * OUTW;

    extern __shared__ char dsm[];
    const uint32_t base = (smem_u32(dsm) + 1023) & ~1023u;
    const uint32_t AH = base, AL = base + 32768, WH = base + 65536, WL = base + 81920;

    const int tid  = threadIdx.x;
    const int lane = tid & 31, w = tid >> 5;
    const int img  = blockIdx.x;
    const int p0   = blockIdx.y * 128;

    const int  p   = p0 + tid;
    const bool pv  = p < NPIX;
    const int  pc  = pv ? p : 0;
    const int  oh2 = 2 * (pc / OUTW) - PAD;
    const int  ow2 = 2 * (pc % OUTW) - PAD;
    const size_t imgbase = (size_t)img * INW * INW * 64;
    const int  wrow = tid >> 1, wc0 = (tid & 1) * 4;

    auto stage = [&](int tap, int sel) {
        const int kh = tap / 3, kw = tap - kh * 3;
        const int ih = oh2 + kh, iw = ow2 + kw;
        const bool valid = pv && (unsigned)ih < (unsigned)INW && (unsigned)iw < (unsigned)INW;
        const uint32_t ssz = valid ? 16u : 0u;
        const size_t off = valid ? (imgbase + ((size_t)ih * INW + iw) * 64) : imgbase;
        const __nv_bfloat16* sh_ = ah + off;
        const __nv_bfloat16* sl_ = al + off;
        const uint32_t dh_ = AH + sel * 16384;
        const uint32_t dl_ = AL + sel * 16384;
#pragma unroll
        for (int c = 0; c < 8; c++) {
            uint32_t d = SWZ(tid * 128 + c * 16);
            cpasync16(dh_ + d, sh_ + c * 8, ssz);
            cpasync16(dl_ + d, sl_ + c * 8, ssz);
        }
        const __nv_bfloat16* wsh = wh + tap * 4096 + wrow * 64 + wc0 * 8;
        const __nv_bfloat16* wsl = wl + tap * 4096 + wrow * 64 + wc0 * 8;
        const uint32_t dwh = WH + sel * 8192, dwl = WL + sel * 8192;
#pragma unroll
        for (int c = 0; c < 4; c++) {
            uint32_t d = SWZ(wrow * 128 + (wc0 + c) * 16);
            cpasync16(dwh + d, wsh + c * 8, 16u);
            cpasync16(dwl + d, wsl + c * 8, 16u);
        }
    };

    float acc[2][8][4];
#pragma unroll
    for (int mt = 0; mt < 2; mt++)
#pragma unroll
        for (int nt = 0; nt < 8; nt++)
#pragma unroll
            for (int q = 0; q < 4; q++) acc[mt][nt][q] = 0.f;

    const int aRow = lane & 15;
    const int aK   = (lane & 16) ? 16 : 0;
    const int bRow = (lane & 7) + ((lane & 16) ? 8 : 0);
    const int bK   = (lane & 8) ? 16 : 0;

    stage(0, 0);
    asm volatile("cp.async.commit_group;" ::: "memory");

    for (int tap = 0; tap < 9; ++tap) {
        const int sel = tap & 1;
        if (tap < 8) {
            stage(tap + 1, sel ^ 1);
            asm volatile("cp.async.commit_group;" ::: "memory");
            asm volatile("cp.async.wait_group 1;" ::: "memory");
        } else {
            asm volatile("cp.async.wait_group 0;" ::: "memory");
        }
        __syncthreads();

        const uint32_t Asel = sel * 16384, Wsel = sel * 8192;
#pragma unroll
        for (int s = 0; s < 3; ++s) {
            const uint32_t Ab = ((s == 1) ? AL : AH) + Asel;
            const uint32_t Bb = ((s == 2) ? WL : WH) + Wsel;
#pragma unroll
            for (int ks = 0; ks < 4; ++ks) {
                const int kb = ks * 32;
                uint32_t bf[8][2];
#pragma unroll
                for (int np = 0; np < 4; ++np) {
                    uint32_t addr = Bb + SWZ((np * 16 + bRow) * 128 + kb + bK);
                    ldsm4(bf[2 * np][0], bf[2 * np][1],
                          bf[2 * np + 1][0], bf[2 * np + 1][1], addr);
                }
#pragma unroll
                for (int mt = 0; mt < 2; ++mt) {
                    uint32_t af[4];
                    uint32_t addr = Ab + SWZ((w * 32 + mt * 16 + aRow) * 128 + kb + aK);
                    ldsm4(af[0], af[1], af[2], af[3], addr);
#pragma unroll
                    for (int nt = 0; nt < 8; ++nt)
                        mma16816(acc[mt][nt], af, bf[nt]);
                }
            }
        }
        __syncthreads();
    }

    // epilogue: bias + relu
#pragma unroll
    for (int mt = 0; mt < 2; ++mt) {
        int r = w * 32 + mt * 16 + (lane >> 2);
#pragma unroll
        for (int half = 0; half < 2; ++half) {
            int pp = p0 + r + half * 8;
            if (pp >= NPIX) continue;
#pragma unroll
            for (int nt = 0; nt < 8; ++nt) {
                int col = nt * 8 + (lane & 3) * 2;
                float v0 = fmaxf(acc[mt][nt][half * 2 + 0] + bias[col],     0.f);
                float v1 = fmaxf(acc[mt][nt][half * 2 + 1] + bias[col + 1], 0.f);
                if (OUT_FP32) {
                    float2* o = (float2*)(outf + ((size_t)img * NPIX + pp) * 64 + col);
                    *o = make_float2(v0, v1);
                } else {
                    __nv_bfloat16 h0, l0, h1, l1;
                    bf16split(v0, h0, l0);
                    bf16split(v1, h1, l1);
                    uint32_t hp = (uint32_t)__bfloat16_as_ushort(h0) |
                                  ((uint32_t)__bfloat16_as_ushort(h1) << 16);
                    uint32_t lp = (uint32_t)__bfloat16_as_ushort(l0) |
                                  ((uint32_t)__bfloat16_as_ushort(l1) << 16);
                    *(uint32_t*)(outh + ((size_t)img * NPIX + pp) * 64 + col) = hp;
                    *(uint32_t*)(outl + ((size_t)img * NPIX + pp) * 64 + col) = lp;
                }
            }
        }
    }
}

// ---------------- prototypes / norms / logits (NHWC order-invariant) ----------------
__global__ void proto_kernel(const float* __restrict__ emb_s, const int* __restrict__ y,
                             float* __restrict__ protos)
{
    int b = blockIdx.x, c = blockIdx.y;
    for (int d = threadIdx.x; d < 2304; d += blockDim.x) {
        float acc = 0.f;
#pragma unroll
        for (int s = 0; s < 25; s++) {
            if ((y[b * 25 + s] % 5) == c)
                acc += emb_s[(size_t)(b * 25 + s) * 2304 + d];
        }
        protos[(size_t)(b * 5 + c) * 2304 + d] = acc * 0.2f;
    }
}

__device__ __forceinline__ float block_reduce(float v, float* red) {
    red[threadIdx.x] = v;
    __syncthreads();
    for (int s = 128; s > 0; s >>= 1) {
        if (threadIdx.x < s) red[threadIdx.x] += red[threadIdx.x + s];
        __syncthreads();
    }
    float r = red[0];
    __syncthreads();
    return r;
}

__global__ void pnorm_kernel(const float* __restrict__ protos, float* __restrict__ pnorm) {
    __shared__ float red[256];
    const float* p = protos + (size_t)blockIdx.x * 2304;
    float s = 0.f;
    for (int d = threadIdx.x; d < 2304; d += 256) { float v = p[d]; s += v * v; }
    float tot = block_reduce(s, red);
    if (threadIdx.x == 0) pnorm[blockIdx.x] = fmaxf(sqrtf(tot), 1e-8f);
}

__global__ void logits_kernel(const float* __restrict__ emb, const float* __restrict__ protos,
                              const float* __restrict__ pnorm, float* __restrict__ out)
{
    __shared__ float red[256];
    int b = blockIdx.x / 75, t = blockIdx.x % 75;
    const float* q = emb + (size_t)(200 + b * 75 + t) * 2304;
    const float* P = protos + (size_t)b * 5 * 2304;

    float q2 = 0.f, dot[5] = {0.f, 0.f, 0.f, 0.f, 0.f};
    for (int d = threadIdx.x; d < 2304; d += 256) {
        float v = q[d];
        q2 += v * v;
#pragma unroll
        for (int c = 0; c < 5; c++) dot[c] += v * P[(size_t)c * 2304 + d];
    }
    float q2t = block_reduce(q2, red);
    float qn  = fmaxf(sqrtf(q2t), 1e-8f);
#pragma unroll
    for (int c = 0; c < 5; c++) {
        float dt = block_reduce(dot[c], red);
        if (threadIdx.x == 0)
            out[(size_t)(b * 75 + t) * 5 + c] = dt / (qn * pnorm[b * 5 + c]);
    }
}

// ---------------- launch ----------------
extern "C" void kernel_launch(void* const* d_in, const int* in_sizes, int n_in,
                              void* d_out, int out_size)
{
    const float* xs = (const float*)d_in[0];
    const float* xt = (const float*)d_in[1];
    const int*   y  = (const int*)  d_in[2];
    const float* W1 = (const float*)d_in[3];
    const float* b1 = (const float*)d_in[4];
    const float* W2 = (const float*)d_in[5];
    const float* b2 = (const float*)d_in[6];
    const float* W3 = (const float*)d_in[7];
    const float* b3 = (const float*)d_in[8];
    const float* W4 = (const float*)d_in[9];
    const float* b4 = (const float*)d_in[10];
    float* out = (float*)d_out;

    float *emb, *protos, *pnorm;
    __nv_bfloat16 *a1h, *a1l, *a2h, *a2l, *a3h, *a3l;
    __nv_bfloat16 *w1h, *w1l, *w2h, *w2l, *w3h, *w3l, *w4h, *w4l;
    cudaGetSymbolAddress((void**)&a1h,    g_a1h);
    cudaGetSymbolAddress((void**)&a1l,    g_a1l);
    cudaGetSymbolAddress((void**)&a2h,    g_a2h);
    cudaGetSymbolAddress((void**)&a2l,    g_a2l);
    cudaGetSymbolAddress((void**)&a3h,    g_a3h);
    cudaGetSymbolAddress((void**)&a3l,    g_a3l);
    cudaGetSymbolAddress((void**)&emb,    g_emb);
    cudaGetSymbolAddress((void**)&w1h,    g_w1h);
    cudaGetSymbolAddress((void**)&w1l,    g_w1l);
    cudaGetSymbolAddress((void**)&w2h,    g_w2h);
    cudaGetSymbolAddress((void**)&w2l,    g_w2l);
    cudaGetSymbolAddress((void**)&w3h,    g_w3h);
    cudaGetSymbolAddress((void**)&w3l,    g_w3l);
    cudaGetSymbolAddress((void**)&w4h,    g_w4h);
    cudaGetSymbolAddress((void**)&w4l,    g_w4l);
    cudaGetSymbolAddress((void**)&protos, g_protos);
    cudaGetSymbolAddress((void**)&pnorm,  g_pnorm);

    auto c2 = conv_mma<42, 21, 0, false>;
    auto c3 = conv_mma<21, 11, 1, false>;
    auto c4 = conv_mma<11, 6,  1, true>;
    const int DSMEM = 98304 + 1024;
    static int attr_done = 0;
    if (!attr_done) {
        cudaFuncSetAttribute((const void*)c2, cudaFuncAttributeMaxDynamicSharedMemorySize, DSMEM);
        cudaFuncSetAttribute((const void*)c3, cudaFuncAttributeMaxDynamicSharedMemorySize, DSMEM);
        cudaFuncSetAttribute((const void*)c4, cudaFuncAttributeMaxDynamicSharedMemorySize, DSMEM);
        attr_done = 1;
    }

    prep_weights<<<(36864 + 255) / 256, 256>>>(W1, W2, W3, W4);

    // L1: single-GEMM mma conv, writes NHWC bf16 hi/lo directly
    conv1_mma<<<dim3(800, 14), 128>>>(xs, xt, w1h, w1l, b1, a1h, a1l);

    // L2-L4: mma.sync implicit-GEMM convs (bf16 3-split, cp.async pipelined)
    c2<<<dim3(800, 4), 128, DSMEM>>>(a1h, a1l, w2h, w2l, b2, a2h, a2l, nullptr);
    c3<<<dim3(800, 1), 128, DSMEM>>>(a2h, a2l, w3h, w3l, b3, a3h, a3l, nullptr);
    c4<<<dim3(800, 1), 128, DSMEM>>>(a3h, a3l, w4h, w4l, b4, nullptr, nullptr, emb);

    proto_kernel<<<dim3(8, 5), 256>>>(emb, y, protos);
    pnorm_kernel<<<40, 256>>>(protos, pnorm);
    logits_kernel<<<600, 256>>>(emb, protos, pnorm, out);
}